// round 7
// baseline (speedup 1.0000x reference)
#include <cuda_runtime.h>
#include <cstdint>

// LSTM decoder, persistent per-CTA recurrence. 256 threads.
// Each thread: 2 hidden units (8 gate rows) + 1 Wo row, over 32 of 128 k's.
// Warp = 8 row-columns x 4 k-groups; k-partials reduced by warp shuffles.
// Cell state c register-resident; gates never touch SMEM.
// B=2048, L=64, H=128, 4H=512, O=64, T=512, fp32.
// Identity: x_t == h_t for t>=1 => gates = h @ (W_ih+W_hh)^T + (b_ih+b_hh).
// t==0: x=0 => gates = h0 @ W_hh^T + (b_ih+b_hh).

typedef unsigned long long ull;

#define Lq   64
#define Hq   128
#define G4   512
#define Oq   64
#define Tq   512
#define NPB  7      // batch pairs per CTA (14 slots)
#define HS   20     // h_s row stride in floats (80 B)

// Quad-packed weights: g_Wq[k*128 + u] = (W[u][k], W[u+128][k], W[u+256][k], W[u+384][k])
__device__ float4 g_Wq [Hq * Hq];   // combined W_ih + W_hh
__device__ float4 g_Whq[Hq * Hq];   // W_hh only (step 0)

// ---------- helpers ----------
__device__ __forceinline__ ull fma2(ull a, ull b, ull c) {
    ull d; asm("fma.rn.f32x2 %0, %1, %2, %3;" : "=l"(d) : "l"(a), "l"(b), "l"(c)); return d;
}
__device__ __forceinline__ ull add2(ull a, ull b) {
    ull d; asm("add.rn.f32x2 %0, %1, %2;" : "=l"(d) : "l"(a), "l"(b)); return d;
}
__device__ __forceinline__ ull dup2(float x) {
    ull d; asm("mov.b64 %0, {%1, %1};" : "=l"(d) : "f"(x)); return d;
}
__device__ __forceinline__ ull pack2(float lo, float hi) {
    ull d; asm("mov.b64 %0, {%1, %2};" : "=l"(d) : "f"(lo), "f"(hi)); return d;
}
__device__ __forceinline__ void unpk(ull a, float& lo, float& hi) {
    asm("mov.b64 {%0, %1}, %2;" : "=f"(lo), "=f"(hi) : "l"(a));
}
__device__ __forceinline__ void ldsv2(ull& a, ull& b, unsigned addr) {
    asm volatile("ld.shared.v2.u64 {%0, %1}, [%2];" : "=l"(a), "=l"(b) : "r"(addr));
}
__device__ __forceinline__ ull lds64(unsigned addr) {
    ull a; asm volatile("ld.shared.u64 %0, [%1];" : "=l"(a) : "r"(addr)); return a;
}
__device__ __forceinline__ void sts64(unsigned addr, ull v) {
    asm volatile("st.shared.u64 [%0], %1;" :: "r"(addr), "l"(v));
}
__device__ __forceinline__ unsigned sm_u32(const void* p) {
    unsigned r;
    asm("{ .reg .u64 t; cvta.to.shared.u64 t, %1; cvt.u32.u64 %0, t; }" : "=r"(r) : "l"(p));
    return r;
}
__device__ __forceinline__ ull shflx64(ull v, int m) {
    return __shfl_xor_sync(0xffffffffu, v, m);
}
__device__ __forceinline__ float sigf(float x)   { return __fdividef(1.f, 1.f + __expf(-x)); }
__device__ __forceinline__ float tanhf2(float x) { return __fdividef(2.f, 1.f + __expf(-2.f * x)) - 1.f; }

// ---------- prep: quad-pack transposed weights ----------
__global__ void decoder_prep(const float* __restrict__ Wih, const float* __restrict__ Whh) {
    int i = blockIdx.x * blockDim.x + threadIdx.x;   // i = k*128 + u
    if (i < Hq * Hq) {
        int u = i & 127, k = i >> 7;
        float4 wh, wc;
        wh.x = Whh[u * Hq + k];          wc.x = Wih[u * Hq + k]          + wh.x;
        wh.y = Whh[(u + 128) * Hq + k];  wc.y = Wih[(u + 128) * Hq + k]  + wh.y;
        wh.z = Whh[(u + 256) * Hq + k];  wc.z = Wih[(u + 256) * Hq + k]  + wh.z;
        wh.w = Whh[(u + 384) * Hq + k];  wc.w = Wih[(u + 384) * Hq + k]  + wh.w;
        g_Wq[i] = wc;  g_Whq[i] = wh;
    }
}

// ---------- big fused GEMM: 8 gate rows + 1 out row over 32 k's ----------
// MODE 0: t==0 (both units LDG from g_Whq). MODE 1: u0 from SMEM, u1 LDG g_Wq.
template <int MODE>
__device__ __forceinline__ void big_gemm(
    const float4* __restrict__ wq_s,   // SMEM, pre-offset (kg*32*64 + u0), stride 64/k
    const float4* __restrict__ wq_g0,  // global g_Whq + kg*32*128 + u0 (MODE 0)
    const float4* __restrict__ wq_g1,  // global (MODE? g_Wq : g_Whq) + kg*32*128 + u1
    const float*  __restrict__ wo_s,   // SMEM Wo_s + kg*32*64 + rc
    unsigned hbk,                      // h_s byte addr + kg*32*80
    ull (&A)[2][4][7], ull (&Aw)[7])
{
#pragma unroll 8
    for (int i = 0; i < 32; i++) {
        float4 w0 = MODE ? wq_s[i * 64] : __ldg(wq_g0 + i * 128);
        float4 w1 = __ldg(wq_g1 + i * 128);
        float  wo = wo_s[i * 64];
        unsigned a = hbk + (unsigned)(i * (HS * 4));
        ull h0, h1, h2, h3, h4, h5, h6;
        ldsv2(h0, h1, a);
        ldsv2(h2, h3, a + 16);
        ldsv2(h4, h5, a + 32);
        h6 = lds64(a + 48);
        ull hh[7] = {h0, h1, h2, h3, h4, h5, h6};
        ull wi0 = dup2(w0.x), wf0 = dup2(w0.y), wg0 = dup2(w0.z), wo0 = dup2(w0.w);
        ull wi1 = dup2(w1.x), wf1 = dup2(w1.y), wg1 = dup2(w1.z), wo1 = dup2(w1.w);
        ull wwo = dup2(wo);
#pragma unroll
        for (int bp = 0; bp < NPB; bp++) {
            A[0][0][bp] = fma2(wi0, hh[bp], A[0][0][bp]);
            A[0][1][bp] = fma2(wf0, hh[bp], A[0][1][bp]);
            A[0][2][bp] = fma2(wg0, hh[bp], A[0][2][bp]);
            A[0][3][bp] = fma2(wo0, hh[bp], A[0][3][bp]);
            A[1][0][bp] = fma2(wi1, hh[bp], A[1][0][bp]);
            A[1][1][bp] = fma2(wf1, hh[bp], A[1][1][bp]);
            A[1][2][bp] = fma2(wg1, hh[bp], A[1][2][bp]);
            A[1][3][bp] = fma2(wo1, hh[bp], A[1][3][bp]);
            Aw[bp]      = fma2(wwo, hh[bp], Aw[bp]);
        }
    }
}

// SMEM layout (float offsets):
//   Wq_s [128k][64u] f4 @ 0      (32768)  quad weights, units 0..63
//   Wo_s [128k][64o]    @ 32768  ( 8192)  Wo transposed
//   h_s  [128][20]      @ 40960  ( 2560)  h transposed [k][slot]
//   ob   [64o][14s]     @ 43520  (  896)  out staging
#define OFF_WOS 32768
#define OFF_H   40960
#define OFF_OB  43520
#define SMEM_FLOATS 44416
#define SMEM_BYTES  (SMEM_FLOATS * 4)

__global__ void __launch_bounds__(256, 1) decoder_main(
    const float* __restrict__ latent, const float* __restrict__ fc_w, const float* __restrict__ fc_b,
    const float* __restrict__ b_ih,   const float* __restrict__ b_hh,
    const float* __restrict__ Wo,     const float* __restrict__ bo,
    float* __restrict__ out)
{
    extern __shared__ float sm[];
    float4* Wq_s = reinterpret_cast<float4*>(sm);
    float* Wo_s = sm + OFF_WOS;
    float* h_s  = sm + OFF_H;
    float* ob   = sm + OFF_OB;

    const int tid  = threadIdx.x;
    const int lane = tid & 31;
    const int warp = tid >> 5;       // 8 warps
    const int kg   = lane >> 3;      // k-group 0..3
    const int kgb0 = kg & 1;
    const int kgb1 = kg >> 1;
    const int rc   = warp * 8 + (lane & 7);   // 0..63
    const int u0   = rc, u1 = rc + 64;
    const int cta  = blockIdx.x;
    int bstart, nb;
    if (cta < 124) { bstart = cta * 14;                nb = 14; }
    else           { bstart = 1736 + (cta - 124) * 13; nb = 13; }

    // Stage quad weights (units 0..63) and Wo into SMEM.
    for (int i = tid; i < Hq * 64; i += 256) {
        int k = i >> 6, u = i & 63;
        Wq_s[i] = g_Wq[k * Hq + u];
    }
    for (int i = tid; i < Hq * Oq; i += 256) {
        int k = i >> 6, o = i & 63;
        Wo_s[i] = Wo[o * Hq + k];
    }
    for (int i = tid; i < Hq * HS; i += 256) h_s[i] = 0.f;
    __syncthreads();

    // h0 = latent @ fc_w^T + fc_b  (pad slots stay 0)
    for (int i = tid; i < 14 * Hq; i += 256) {
        int slot = i >> 7, hk = i & 127;
        float acc = 0.f;
        if (slot < nb) {
            acc = fc_b[hk];
            const float* lp = latent + (size_t)(bstart + slot) * Lq;
            const float* wp = fc_w + hk * Lq;
#pragma unroll 8
            for (int l = 0; l < Lq; l++) acc += lp[l] * wp[l];
        }
        h_s[hk * HS + slot] = acc;
    }

    // Biases (only kg==0 lanes carry them into the k-sum).
    ull bb[2][4];
#pragma unroll
    for (int us = 0; us < 2; us++) {
        int u = us ? u1 : u0;
#pragma unroll
        for (int g = 0; g < 4; g++) {
            float v = b_ih[g * 128 + u] + b_hh[g * 128 + u];
            bb[us][g] = (kg == 0) ? dup2(v) : 0ull;
        }
    }
    const ull bow = (kg == 0) ? dup2(bo[rc]) : 0ull;

    // Register-resident cell state for this lane's owned (unit, bp) cells.
    ull cR[4] = {0ull, 0ull, 0ull, 0ull};
    const int U = kgb1 ? u1 : u0;    // owned unit after stage-A reduction

    const unsigned hb  = sm_u32(h_s);
    const unsigned obb = sm_u32(ob);
    const unsigned hbk = hb + (unsigned)(kg * 32 * (HS * 4));
    const float4* wq_sp = Wq_s  + kg * 32 * 64 + u0;
    const float4* wh_g0 = g_Whq + kg * 32 * Hq + u0;
    const float4* wh_g1 = g_Whq + kg * 32 * Hq + u1;
    const float4* wc_g1 = g_Wq  + kg * 32 * Hq + u1;
    const float*  wo_sp = Wo_s  + kg * 32 * 64 + rc;
    __syncthreads();

    for (int t = 0; t < Tq; t++) {
        // ---- phase 1: fused gate+out GEMM over this lane's 32 k's ----
        ull A[2][4][7], Aw[7];
#pragma unroll
        for (int us = 0; us < 2; us++)
#pragma unroll
            for (int g = 0; g < 4; g++)
#pragma unroll
                for (int bp = 0; bp < NPB; bp++) A[us][g][bp] = bb[us][g];
#pragma unroll
        for (int bp = 0; bp < NPB; bp++) Aw[bp] = bow;

        if (t == 0) big_gemm<0>(wq_sp, wh_g0, wh_g1, wo_sp, hbk, A, Aw);
        else        big_gemm<1>(wq_sp, wh_g0, wc_g1, wo_sp, hbk, A, Aw);

        // ---- warp-shuffle reduce-scatter over k-groups ----
        // Stage A (xor 16): keep own unit (kgb1), receive partner's partial of it.
        ull K[4][7];
#pragma unroll
        for (int g = 0; g < 4; g++)
#pragma unroll
            for (int bp = 0; bp < NPB; bp++) {
                ull snd  = kgb1 ? A[0][g][bp] : A[1][g][bp];
                ull rcv  = shflx64(snd, 16);
                ull mine = kgb1 ? A[1][g][bp] : A[0][g][bp];
                K[g][bp] = add2(mine, rcv);
            }
#pragma unroll
        for (int bp = 0; bp < NPB; bp++) Aw[bp] = add2(Aw[bp], shflx64(Aw[bp], 16));

        // Stage B (xor 8): keep bp 0..3 (kgb0==0) or bp 4..6 (kgb0==1).
#pragma unroll
        for (int g = 0; g < 4; g++)
#pragma unroll
            for (int j = 0; j < 4; j++) {
                ull snd = kgb0 ? K[g][j] : ((j < 3) ? K[g][4 + j] : K[g][0]);
                ull rcv = shflx64(snd, 8);
                if (!kgb0)          K[g][j]     = add2(K[g][j],     rcv);
                else if (j < 3)     K[g][4 + j] = add2(K[g][4 + j], rcv);
            }
#pragma unroll
        for (int bp = 0; bp < NPB; bp++) Aw[bp] = add2(Aw[bp], shflx64(Aw[bp], 8));

        __syncthreads();   // all h_s reads of this step done

        // ---- phase 2: elementwise cell update in registers; write h to SMEM ----
#pragma unroll
        for (int j = 0; j < 4; j++) {
            int bp = kgb0 ? 4 + j : j;
            if (!kgb0 || j < 3) {
                float gi0, gi1, gf0, gf1, gg0, gg1, go0, go1, cc0, cc1;
                unpk(K[0][bp], gi0, gi1);
                unpk(K[1][bp], gf0, gf1);
                unpk(K[2][bp], gg0, gg1);
                unpk(K[3][bp], go0, go1);
                unpk(cR[j], cc0, cc1);
                float nc0 = sigf(gf0) * cc0 + sigf(gi0) * tanhf2(gg0);
                float nc1 = sigf(gf1) * cc1 + sigf(gi1) * tanhf2(gg1);
                float hv0 = sigf(go0) * tanhf2(nc0);
                float hv1 = sigf(go1) * tanhf2(nc1);
                cR[j] = pack2(nc0, nc1);
                sts64(hb + (unsigned)(U * (HS * 4) + bp * 8), pack2(hv0, hv1));
            }
        }

        // ---- stage out[t-1] (full sums on all lanes; kg 0/1 write) ----
        if (kg < 2) {
#pragma unroll
            for (int j = 0; j < 4; j++) {
                int bp = kgb0 ? 4 + j : j;
                if (!kgb0 || j < 3)
                    sts64(obb + (unsigned)(rc * 56 + bp * 8), Aw[bp]);
            }
        }
        __syncthreads();

        // ---- coalesced store of out[t-1] ----
        if (t > 0 && warp < 7) {
            int o2 = 2 * lane;
#pragma unroll
            for (int si = 0; si < 2; si++) {
                int s = 2 * warp + si;
                if (s < nb) {
                    float va = ob[o2 * 14 + s];
                    float vb = ob[(o2 + 1) * 14 + s];
                    *reinterpret_cast<float2*>(
                        out + ((size_t)(bstart + s) * Tq + (t - 1)) * Oq + o2) =
                        make_float2(va, vb);
                }
            }
        }
    }

    // ---- tail: out[T-1] from final h ----
    {
        ull Aw[7];
#pragma unroll
        for (int bp = 0; bp < NPB; bp++) Aw[bp] = bow;
#pragma unroll 8
        for (int i = 0; i < 32; i++) {
            float wo = wo_sp[i * 64];
            ull w = dup2(wo);
            unsigned a = hbk + (unsigned)(i * (HS * 4));
            ull h0, h1, h2, h3, h4, h5, h6;
            ldsv2(h0, h1, a);
            ldsv2(h2, h3, a + 16);
            ldsv2(h4, h5, a + 32);
            h6 = lds64(a + 48);
            ull hh[7] = {h0, h1, h2, h3, h4, h5, h6};
#pragma unroll
            for (int bp = 0; bp < NPB; bp++) Aw[bp] = fma2(w, hh[bp], Aw[bp]);
        }
#pragma unroll
        for (int bp = 0; bp < NPB; bp++) Aw[bp] = add2(Aw[bp], shflx64(Aw[bp], 16));
#pragma unroll
        for (int bp = 0; bp < NPB; bp++) Aw[bp] = add2(Aw[bp], shflx64(Aw[bp], 8));

        // RACE FIX: ensure all warps are done READING ob (out[T-2] store above)
        // before the tail overwrites it.
        __syncthreads();

        if (kg < 2) {
#pragma unroll
            for (int j = 0; j < 4; j++) {
                int bp = kgb0 ? 4 + j : j;
                if (!kgb0 || j < 3)
                    sts64(obb + (unsigned)(rc * 56 + bp * 8), Aw[bp]);
            }
        }
        __syncthreads();
        if (warp < 7) {
            int o2 = 2 * lane;
#pragma unroll
            for (int si = 0; si < 2; si++) {
                int s = 2 * warp + si;
                if (s < nb) {
                    float va = ob[o2 * 14 + s];
                    float vb = ob[(o2 + 1) * 14 + s];
                    *reinterpret_cast<float2*>(
                        out + ((size_t)(bstart + s) * Tq + (Tq - 1)) * Oq + o2) =
                        make_float2(va, vb);
                }
            }
        }
    }
}

extern "C" void kernel_launch(void* const* d_in, const int* in_sizes, int n_in,
                              void* d_out, int out_size) {
    const float* latent = (const float*)d_in[0];
    const float* fc_w   = (const float*)d_in[1];
    const float* fc_b   = (const float*)d_in[2];
    const float* W_ih   = (const float*)d_in[3];
    const float* W_hh   = (const float*)d_in[4];
    const float* b_ih   = (const float*)d_in[5];
    const float* b_hh   = (const float*)d_in[6];
    const float* Wo     = (const float*)d_in[7];
    const float* bo     = (const float*)d_in[8];
    float* out = (float*)d_out;

    cudaFuncSetAttribute(decoder_main,
                         cudaFuncAttributeMaxDynamicSharedMemorySize, SMEM_BYTES);

    decoder_prep<<<(Hq * Hq + 255) / 256, 256>>>(W_ih, W_hh);
    decoder_main<<<148, 256, SMEM_BYTES>>>(latent, fc_w, fc_b, b_ih, b_hh, Wo, bo, out);
}